// round 1
// baseline (speedup 1.0000x reference)
#include <cuda_runtime.h>
#include <math.h>

// ---------------------------------------------------------------------------
// Waveletnet: 4-level Haar wavelet U-Net, fp32 direct implementation.
// Shapes: x (16,3,256,256) -> y (16,2,256,256)
// ---------------------------------------------------------------------------

#define NB 16

// Static scratch (allocation-free rule: __device__ globals)
__device__ float g_c1 [4194304];   // 16x16x128x128
__device__ float g_c2 [4194304];   // 16x64x64x64
__device__ float g_c3 [4194304];   // 16x256x32x32
__device__ float g_w4 [4194304];   // 16x1024x16x16
__device__ float g_t0 [4194304];
__device__ float g_t1 [4194304];
__device__ float g_big[8388608];   // concat buffers (iw4/iw3/iw2 are all 8.39M)
__device__ float g_wsw[9437184];   // standardized weights scratch (max 1024*1024*9)

// ---------------------------------------------------------------------------
// Weight standardization: per output filter, mean over K elems, unbiased std.
// wout = (w - mean) / (sqrt(ss/(K-1)) + 1e-5)
// ---------------------------------------------------------------------------
__global__ void ws_kernel(const float* __restrict__ w, float* __restrict__ out, int K)
{
    int f = blockIdx.x;
    const float* wf = w + (size_t)f * K;
    __shared__ float red[256];
    float s = 0.f;
    for (int i = threadIdx.x; i < K; i += 256) s += wf[i];
    red[threadIdx.x] = s; __syncthreads();
    for (int o = 128; o; o >>= 1) {
        if (threadIdx.x < o) red[threadIdx.x] += red[threadIdx.x + o];
        __syncthreads();
    }
    float mean = red[0] / (float)K;
    __syncthreads();
    float ss = 0.f;
    for (int i = threadIdx.x; i < K; i += 256) { float d = wf[i] - mean; ss += d * d; }
    red[threadIdx.x] = ss; __syncthreads();
    for (int o = 128; o; o >>= 1) {
        if (threadIdx.x < o) red[threadIdx.x] += red[threadIdx.x + o];
        __syncthreads();
    }
    float inv = 1.0f / (sqrtf(red[0] / (float)(K - 1)) + 1e-5f);
    for (int i = threadIdx.x; i < K; i += 256)
        out[(size_t)f * K + i] = (wf[i] - mean) * inv;
}

// ---------------------------------------------------------------------------
// GroupNorm, in place. One block per (n, group).
// ---------------------------------------------------------------------------
__global__ void gn_kernel(float* __restrict__ x, const float* __restrict__ gamma,
                          const float* __restrict__ beta, int C, int HW, int G)
{
    int n = blockIdx.x / G, grp = blockIdx.x % G;
    int cpg = C / G;
    int len = cpg * HW;
    size_t base = ((size_t)n * C + (size_t)grp * cpg) * HW;
    __shared__ float r1[256], r2[256];
    float s = 0.f, ss = 0.f;
    for (int i = threadIdx.x; i < len; i += 256) {
        float v = x[base + i];
        s += v; ss += v * v;
    }
    r1[threadIdx.x] = s; r2[threadIdx.x] = ss; __syncthreads();
    for (int o = 128; o; o >>= 1) {
        if (threadIdx.x < o) { r1[threadIdx.x] += r1[threadIdx.x + o]; r2[threadIdx.x] += r2[threadIdx.x + o]; }
        __syncthreads();
    }
    float mean = r1[0] / (float)len;
    float var  = r2[0] / (float)len - mean * mean;
    float inv  = rsqrtf(var + 1e-5f);
    for (int i = threadIdx.x; i < len; i += 256) {
        int c = grp * cpg + i / HW;
        x[base + i] = (x[base + i] - mean) * inv * gamma[c] + beta[c];
    }
}

// ---------------------------------------------------------------------------
// Haar wavelet forward: (N,C,H,W) -> (N,4C,H/2,W/2), detail remap (r+1)/2
// ---------------------------------------------------------------------------
__global__ void wt_kernel(const float* __restrict__ in, float* __restrict__ out,
                          int C, int H, int W)
{
    int h2 = H >> 1, w2 = W >> 1;
    size_t total = (size_t)NB * C * h2 * w2;
    for (size_t idx = (size_t)blockIdx.x * blockDim.x + threadIdx.x; idx < total;
         idx += (size_t)gridDim.x * blockDim.x) {
        int j = (int)(idx % w2); size_t t = idx / w2;
        int i = (int)(t % h2); t /= h2;
        int c = (int)(t % C); int n = (int)(t / C);
        const float* p = in + ((size_t)(n * C + c) * H + 2 * i) * W + 2 * j;
        float a = p[0], b = p[1], cc = p[W], d = p[W + 1];
        size_t cs = (size_t)h2 * w2;
        size_t ob = (((size_t)n * 4 * C + 4 * c) * h2 + i) * w2 + j;
        out[ob]          = 0.25f * (a + b + cc + d);
        out[ob + cs]     = 0.25f * (a + b - cc - d) + 0.5f;
        out[ob + 2 * cs] = 0.25f * (a - b + cc - d) + 0.5f;
        out[ob + 3 * cs] = 0.25f * (a - b - cc + d) + 0.5f;
    }
}

// ---------------------------------------------------------------------------
// Haar inverse: input (N,4C,h,w), details remap 2v-1, scatter to 2x2 blocks.
// Writes into output buffer with channel offset (for concat) and total Cdst.
// ---------------------------------------------------------------------------
__global__ void iwt_kernel(const float* __restrict__ in, float* __restrict__ out,
                           int C, int h, int w, int c_off, int Cdst)
{
    size_t total = (size_t)NB * C * h * w;
    for (size_t idx = (size_t)blockIdx.x * blockDim.x + threadIdx.x; idx < total;
         idx += (size_t)gridDim.x * blockDim.x) {
        int j = (int)(idx % w); size_t t = idx / w;
        int i = (int)(t % h); t /= h;
        int c = (int)(t % C); int n = (int)(t / C);
        size_t cs = (size_t)h * w;
        size_t ib = (((size_t)n * 4 * C + 4 * c) * h + i) * w + j;
        float s0 = in[ib];
        float s1 = 2.f * in[ib + cs]     - 1.f;
        float s2 = 2.f * in[ib + 2 * cs] - 1.f;
        float s3 = 2.f * in[ib + 3 * cs] - 1.f;
        float* q = out + (((size_t)n * Cdst + c_off + c) * 2 * h + 2 * i) * 2 * w + 2 * j;
        q[0]         = s0 + 0.5f * ( s1 + s2 + s3);
        q[1]         = s0 + 0.5f * ( s1 - s2 - s3);
        q[2 * w]     = s0 + 0.5f * (-s1 + s2 - s3);
        q[2 * w + 1] = s0 + 0.5f * (-s1 - s2 + s3);
    }
}

// ---------------------------------------------------------------------------
// Channel-offset copy (for skip concatenation)
// ---------------------------------------------------------------------------
__global__ void copy_ch_kernel(const float* __restrict__ src, float* __restrict__ dst,
                               int C, int HW, int Cdst, int c_off)
{
    size_t total = (size_t)NB * C * HW;
    for (size_t idx = (size_t)blockIdx.x * blockDim.x + threadIdx.x; idx < total;
         idx += (size_t)gridDim.x * blockDim.x) {
        int p = (int)(idx % HW); size_t t = idx / HW;
        int c = (int)(t % C); int n = (int)(t / C);
        dst[((size_t)n * Cdst + c_off + c) * HW + p] = src[idx];
    }
}

// ---------------------------------------------------------------------------
// Direct 3x3 conv, pad 1, NCHW fp32. 16x16 spatial tile x 32 out-channels per
// block. 256 threads: 4 co-groups x 64 pixel-threads; each thread: 8 co x 4 px
// accumulators (32 FMA per 6 shared loads). Fused bias / skip / lrelu.
// ---------------------------------------------------------------------------
__global__ __launch_bounds__(256) void conv3x3_kernel(
    const float* __restrict__ in, const float* __restrict__ wgt,
    const float* __restrict__ bias, const float* __restrict__ skip,
    float* __restrict__ out, int Cin, int Cout, int H, int W, int do_lrelu)
{
    __shared__ __align__(16) float s_in[4][18][18];
    __shared__ __align__(16) float s_w[4][9][32];

    int tiles_x = W >> 4;
    int tx0 = (blockIdx.x % tiles_x) << 4;
    int ty0 = (blockIdx.x / tiles_x) << 4;
    int co_base = blockIdx.y << 5;
    int n = blockIdx.z;
    int tx = threadIdx.x;
    int cog8 = (tx >> 6) << 3;      // 0,8,16,24
    int pid  = tx & 63;
    int prow = pid >> 2;            // 0..15
    int pcol = (pid & 3) << 2;      // 0,4,8,12

    float acc[8][4];
#pragma unroll
    for (int r = 0; r < 8; r++)
#pragma unroll
        for (int p = 0; p < 4; p++) acc[r][p] = 0.f;

    for (int cc = 0; cc < Cin; cc += 4) {
        // weights -> smem [ci][tap][co]
        for (int idx = tx; idx < 4 * 9 * 32; idx += 256) {
            int co = idx & 31;
            int tap = (idx >> 5) % 9;
            int ci = (idx >> 5) / 9;
            float v = 0.f;
            if (co_base + co < Cout && cc + ci < Cin)
                v = wgt[((size_t)(co_base + co) * Cin + cc + ci) * 9 + tap];
            s_w[ci][tap][co] = v;
        }
        // input tile + halo -> smem
        for (int idx = tx; idx < 4 * 18 * 18; idx += 256) {
            int ix = idx % 18; int t = idx / 18;
            int iy = t % 18;  int ci = t / 18;
            int gy = ty0 + iy - 1, gx = tx0 + ix - 1;
            float v = 0.f;
            if (cc + ci < Cin && gy >= 0 && gy < H && gx >= 0 && gx < W)
                v = in[((size_t)(n * Cin + cc + ci) * H + gy) * W + gx];
            s_in[ci][iy][ix] = v;
        }
        __syncthreads();

#pragma unroll
        for (int ci = 0; ci < 4; ci++) {
#pragma unroll
            for (int dy = 0; dy < 3; dy++) {
#pragma unroll
                for (int dx = 0; dx < 3; dx++) {
                    float xv[4];
#pragma unroll
                    for (int p = 0; p < 4; p++) xv[p] = s_in[ci][prow + dy][pcol + dx + p];
                    const float* wp = &s_w[ci][dy * 3 + dx][cog8];
                    float4 wa = *reinterpret_cast<const float4*>(wp);
                    float4 wb = *reinterpret_cast<const float4*>(wp + 4);
                    float wv[8] = {wa.x, wa.y, wa.z, wa.w, wb.x, wb.y, wb.z, wb.w};
#pragma unroll
                    for (int r = 0; r < 8; r++)
#pragma unroll
                        for (int p = 0; p < 4; p++) acc[r][p] = fmaf(wv[r], xv[p], acc[r][p]);
                }
            }
        }
        __syncthreads();
    }

    int oy = ty0 + prow;
#pragma unroll
    for (int r = 0; r < 8; r++) {
        int co = co_base + cog8 + r;
        if (co < Cout) {
            float b = bias ? bias[co] : 0.f;
            size_t ob = ((size_t)(n * Cout + co) * H + oy) * W + tx0 + pcol;
#pragma unroll
            for (int p = 0; p < 4; p++) {
                float v = acc[r][p] + b;
                if (skip) v += skip[ob + p];
                if (do_lrelu) v = v > 0.f ? v : 0.2f * v;
                out[ob + p] = v;
            }
        }
    }
}

// ---------------------------------------------------------------------------
// Final 1x1 conv: (N,3,HW) x (2,3) -> (N,2,HW), no bias.
// ---------------------------------------------------------------------------
__global__ void final_kernel(const float* __restrict__ in, const float* __restrict__ w,
                             float* __restrict__ out, int HW)
{
    size_t total = (size_t)NB * HW;
    for (size_t idx = (size_t)blockIdx.x * blockDim.x + threadIdx.x; idx < total;
         idx += (size_t)gridDim.x * blockDim.x) {
        int p = (int)(idx % HW); int n = (int)(idx / HW);
        const float* ip = in + (size_t)n * 3 * HW + p;
        float x0 = ip[0], x1 = ip[HW], x2 = ip[2 * HW];
        float* op = out + (size_t)n * 2 * HW + p;
        op[0]  = w[0] * x0 + w[1] * x1 + w[2] * x2;
        op[HW] = w[3] * x0 + w[4] * x1 + w[5] * x2;
    }
}

// ---------------------------------------------------------------------------
// Host orchestration
// ---------------------------------------------------------------------------
static inline int blocks_for(size_t n) { return (int)((n + 255) / 256); }

extern "C" void kernel_launch(void* const* d_in, const int* in_sizes, int n_in,
                              void* d_out, int out_size)
{
    const float* x        = (const float*)d_in[0];
    const float* conv1_w  = (const float*)d_in[1];  const float* conv1_b  = (const float*)d_in[2];
    const float* conv2_w  = (const float*)d_in[3];  const float* conv2_b  = (const float*)d_in[4];
    const float* conv3_w  = (const float*)d_in[5];  const float* conv3_b  = (const float*)d_in[6];
    const float* conv4_w  = (const float*)d_in[7];  const float* conv4_b  = (const float*)d_in[8];
    const float* convd1_w = (const float*)d_in[9];  const float* convd1_b = (const float*)d_in[10];
    const float* convd2_w = (const float*)d_in[11]; const float* convd2_b = (const float*)d_in[12];
    const float* convd3_w = (const float*)d_in[13]; const float* convd3_b = (const float*)d_in[14];
    const float* convd4_w = (const float*)d_in[15]; const float* convd4_b = (const float*)d_in[16];
    const float* final_w  = (const float*)d_in[17];
    const float* gn1_w = (const float*)d_in[18]; const float* gn1_b = (const float*)d_in[19];
    const float* gn2_w = (const float*)d_in[20]; const float* gn2_b = (const float*)d_in[21];
    const float* gn3_w = (const float*)d_in[22]; const float* gn3_b = (const float*)d_in[23];
    const float* gn4_w = (const float*)d_in[24]; const float* gn4_b = (const float*)d_in[25];

    float *c1, *c2, *c3, *w4, *t0, *t1, *big, *wsw;
    cudaGetSymbolAddress((void**)&c1,  g_c1);
    cudaGetSymbolAddress((void**)&c2,  g_c2);
    cudaGetSymbolAddress((void**)&c3,  g_c3);
    cudaGetSymbolAddress((void**)&w4,  g_w4);
    cudaGetSymbolAddress((void**)&t0,  g_t0);
    cudaGetSymbolAddress((void**)&t1,  g_t1);
    cudaGetSymbolAddress((void**)&big, g_big);
    cudaGetSymbolAddress((void**)&wsw, g_wsw);

    auto conv = [&](const float* in, const float* b, const float* skip, float* out,
                    int Cin, int Cout, int H, int W, bool lr) {
        dim3 g((H / 16) * (W / 16), (Cout + 31) / 32, NB);
        conv3x3_kernel<<<g, 256>>>(in, wsw, b, skip, out, Cin, Cout, H, W, lr ? 1 : 0);
    };

    // ---------------- encoder ----------------
    // w1 = wt(x): (16,12,128,128)
    wt_kernel<<<blocks_for((size_t)NB * 3 * 128 * 128), 256>>>(x, t0, 3, 256, 256);
    ws_kernel<<<16, 256>>>(conv1_w, wsw, 12 * 9);
    conv(t0, conv1_b, nullptr, c1, 12, 16, 128, 128, true);
    gn_kernel<<<NB * 2, 256>>>(c1, gn1_w, gn1_b, 16, 128 * 128, 2);

    // w2 = wt(c1): (16,64,64,64)
    wt_kernel<<<blocks_for((size_t)NB * 16 * 64 * 64), 256>>>(c1, t0, 16, 128, 128);
    ws_kernel<<<64, 256>>>(conv2_w, wsw, 64 * 9);
    conv(t0, conv2_b, nullptr, c2, 64, 64, 64, 64, true);
    gn_kernel<<<NB * 8, 256>>>(c2, gn2_w, gn2_b, 64, 64 * 64, 8);

    // w3 = wt(c2): (16,256,32,32)
    wt_kernel<<<blocks_for((size_t)NB * 64 * 32 * 32), 256>>>(c2, t0, 64, 64, 64);
    ws_kernel<<<256, 256>>>(conv3_w, wsw, 256 * 9);
    conv(t0, conv3_b, nullptr, c3, 256, 256, 32, 32, true);
    gn_kernel<<<NB * 32, 256>>>(c3, gn3_w, gn3_b, 256, 32 * 32, 32);

    // w4 = wt(c3): (16,1024,16,16)
    wt_kernel<<<blocks_for((size_t)NB * 256 * 16 * 16), 256>>>(c3, w4, 256, 32, 32);
    ws_kernel<<<1024, 256>>>(conv4_w, wsw, 1024 * 9);
    // c4
    conv(w4, conv4_b, nullptr, t0, 1024, 1024, 16, 16, true);
    gn_kernel<<<NB * 128, 256>>>(t0, gn4_w, gn4_b, 1024, 16 * 16, 128);
    // c5
    conv(t0, conv4_b, nullptr, t1, 1024, 1024, 16, 16, true);
    gn_kernel<<<NB * 128, 256>>>(t1, gn4_w, gn4_b, 1024, 16 * 16, 128);
    // ic4 = lrelu(c6 + w4)  (c6 = conv + bias, then skip add, then lrelu)
    conv(t1, conv4_b, w4, t0, 1024, 1024, 16, 16, true);

    // ---------------- decoder ----------------
    // iw4 = concat([c3, iwt(ic4)]) : (16,512,32,32)
    iwt_kernel<<<blocks_for((size_t)NB * 256 * 16 * 16), 256>>>(t0, big, 256, 16, 16, 256, 512);
    copy_ch_kernel<<<blocks_for((size_t)NB * 256 * 1024), 256>>>(c3, big, 256, 32 * 32, 512, 0);
    ws_kernel<<<256, 256>>>(convd4_w, wsw, 512 * 9);
    conv(big, convd4_b, nullptr, t1, 512, 256, 32, 32, true);
    gn_kernel<<<NB * 32, 256>>>(t1, gn3_w, gn3_b, 256, 32 * 32, 32);   // ic3

    // iw3 = concat([c2, iwt(ic3)]) : (16,128,64,64)
    iwt_kernel<<<blocks_for((size_t)NB * 64 * 32 * 32), 256>>>(t1, big, 64, 32, 32, 64, 128);
    copy_ch_kernel<<<blocks_for((size_t)NB * 64 * 4096), 256>>>(c2, big, 64, 64 * 64, 128, 0);
    ws_kernel<<<64, 256>>>(convd3_w, wsw, 128 * 9);
    conv(big, convd3_b, nullptr, t0, 128, 64, 64, 64, true);
    gn_kernel<<<NB * 8, 256>>>(t0, gn2_w, gn2_b, 64, 64 * 64, 8);      // ic2

    // iw2 = concat([c1, iwt(ic2)]) : (16,32,128,128)
    iwt_kernel<<<blocks_for((size_t)NB * 16 * 64 * 64), 256>>>(t0, big, 16, 64, 64, 16, 32);
    copy_ch_kernel<<<blocks_for((size_t)NB * 16 * 16384), 256>>>(c1, big, 16, 128 * 128, 32, 0);
    ws_kernel<<<16, 256>>>(convd2_w, wsw, 32 * 9);
    conv(big, convd2_b, nullptr, t1, 32, 16, 128, 128, true);
    gn_kernel<<<NB * 2, 256>>>(t1, gn1_w, gn1_b, 16, 128 * 128, 2);    // ic1

    // iw1 = lrelu(convd1(ic1)) : (16,12,128,128)
    ws_kernel<<<12, 256>>>(convd1_w, wsw, 16 * 9);
    conv(t1, convd1_b, nullptr, t0, 16, 12, 128, 128, true);

    // iwt(iw1): (16,3,256,256)
    iwt_kernel<<<blocks_for((size_t)NB * 3 * 128 * 128), 256>>>(t0, t1, 3, 128, 128, 0, 3);

    // y = ws_conv(., final_w (2,3,1,1), no bias)
    ws_kernel<<<2, 256>>>(final_w, wsw, 3);
    final_kernel<<<blocks_for((size_t)NB * 256 * 256), 256>>>(t1, wsw, (float*)d_out, 256 * 256);
}